// round 13
// baseline (speedup 1.0000x reference)
#include <cuda_runtime.h>
#include <cuda_fp16.h>
#include <cstdint>

// ============================================================================
// Problem constants
// ============================================================================
#define B_DIM  2
#define N_DIM  1024
#define M_DIM  256
#define D_DIM  576
#define H1_DIM 512
#define H2_DIM 256

// Scratch (allocation-free rule: __device__ globals)
// aprojh / bprojh are stored K-PERMUTED: within each 16-column block, the
// half2 pair for logical k-pair p (pairs 0..7) lives at slot (p&3)*2+(p>>2).
// Each mma-lane's two half2s (k0,k0+1),(k0+8,k0+9) are then one LDS.64.
__device__ __half g_aprojh[B_DIM * N_DIM * H1_DIM];   // fp16(a_proj), k-permuted
__device__ __half g_bprojh[B_DIM * M_DIM * H1_DIM];   // fp16(b_proj + b1), k-permuted
__device__ uint4  g_w2frag[32 * 16 * 32];             // W2  pre-packed mma B-fragments
__device__ uint4  g_w1afrag[36 * 32 * 32];            // W1a pre-packed mma B-fragments
__device__ uint4  g_w1bfrag[36 * 32 * 32];            // W1b pre-packed mma B-fragments

// storage half-index of the pair starting at even logical column c
__host__ __device__ __forceinline__ int permslot(int c) {
    int p = (c & 15) >> 1;
    return (c & ~15) + (((p & 3) * 2 + (p >> 2)) << 1);
}

// ============================================================================
// PTX helpers (base ISA — harness compiles for compute_103, no 'a' features)
// ============================================================================
__device__ __forceinline__ uint32_t smem_to_u32(const void* p) {
    uint32_t a;
    asm("{ .reg .u64 t; cvta.to.shared.u64 t, %1; cvt.u32.u64 %0, t; }" : "=r"(a) : "l"(p));
    return a;
}

__device__ __forceinline__ void cp16(uint32_t s, const void* g) {
    asm volatile("cp.async.cg.shared.global [%0], [%1], 16;" :: "r"(s), "l"(g) : "memory");
}
__device__ __forceinline__ void cp_commit() {
    asm volatile("cp.async.commit_group;" ::: "memory");
}

__device__ __forceinline__ void mma_f16(float* c, const uint32_t* a, uint32_t b0, uint32_t b1) {
    asm volatile(
        "mma.sync.aligned.m16n8k16.row.col.f32.f16.f16.f32 "
        "{%0,%1,%2,%3}, {%4,%5,%6,%7}, {%8,%9}, {%0,%1,%2,%3};"
        : "+f"(c[0]), "+f"(c[1]), "+f"(c[2]), "+f"(c[3])
        : "r"(a[0]), "r"(a[1]), "r"(a[2]), "r"(a[3]), "r"(b0), "r"(b1));
}

// h1 fragment: fp16 relu(a + b), 2 ops (HADD2 + HMAX2)
__device__ __forceinline__ uint32_t fragAB(uint32_t a, uint32_t b) {
    __half2 z = __float2half2_rn(0.0f);
    __half2 h = __hmax2(__hadd2(*(__half2*)&a, *(__half2*)&b), z);
    return *(uint32_t*)&h;
}

__device__ __forceinline__ uint32_t packh2(float2 v) {
    __half2 h = __floats2half2_rn(v.x, v.y);
    return *(uint32_t*)&h;
}

// ============================================================================
// Prep A: fragment ALL weight matrices into mma B-operand layout (fp16).
//   z=0: W2  [512][256] -> w2f  (kb<32, jbp<16)
//   z=1: W1a [576][512] -> w1af   z=2: W1b [576][512] -> w1bf
// ============================================================================
__global__ void wfrag_kernel(
    const float* __restrict__ W2, const float* __restrict__ W1a,
    const float* __restrict__ W1b,
    uint4* __restrict__ w2f, uint4* __restrict__ w1af, uint4* __restrict__ w1bf)
{
    const int kb = blockIdx.x, jbp = blockIdx.y, z = blockIdx.z;
    const int lid = threadIdx.x;
    const float* W;
    uint4* out;
    int stride, outidx;
    if (z == 0) {
        if (kb >= 32 || jbp >= 16) return;
        W = W2; out = w2f; stride = H2_DIM;
        outidx = (kb * 16 + jbp) * 32 + lid;
    } else {
        W = (z == 1) ? W1a : W1b;
        out = (z == 1) ? w1af : w1bf;
        stride = H1_DIM;
        outidx = (kb * 32 + jbp) * 32 + lid;
    }
    const int gg = lid >> 2, tg = lid & 3;
    const int k0 = kb * 16 + 2 * tg;
    const int j0 = jbp * 16 + gg;

    auto p2 = [&](int k, int j) {
        __half2 h = __floats2half2_rn(W[(size_t)k * stride + j],
                                      W[(size_t)(k + 1) * stride + j]);
        return *(uint32_t*)&h;
    };
    uint4 u;
    u.x = p2(k0, j0);
    u.y = p2(k0 + 8, j0);
    u.z = p2(k0, j0 + 8);
    u.w = p2(k0 + 8, j0 + 8);
    out[outidx] = u;
}

// ============================================================================
// Prep B: projection GEMMs on tensor cores.
// ============================================================================
__global__ __launch_bounds__(128) void proj_mma_kernel(
    const float* __restrict__ PhiA, const float* __restrict__ PhiB,
    const float* __restrict__ b1,
    const uint4* __restrict__ w1af, const uint4* __restrict__ w1bf,
    __half* __restrict__ aprojh, __half* __restrict__ bprojh)
{
    const int tid = threadIdx.x;
    const int wid = tid >> 5, lid = tid & 31;
    const int g = lid >> 2, tg = lid & 3;
    const int m0 = blockIdx.x * 32;
    const bool isB = m0 >= (B_DIM * N_DIM);
    const float* X = isB ? PhiB : PhiA;
    const int mloc = isB ? m0 - B_DIM * N_DIM : m0;
    const uint4* wf = isB ? w1bf : w1af;
    const int j0 = blockIdx.y * 128 + wid * 32;
    const int jbp0 = j0 >> 4;

    const float* Xr = X + (size_t)(mloc + g) * D_DIM;

    float acc[2][4][4] = {};

    uint4 bf0[2], bf1[2];
    auto ldB = [&](uint4* d, int kb) {
        const int fb = (kb * 32 + jbp0) * 32 + lid;
        d[0] = wf[fb];
        d[1] = wf[fb + 32];
    };
    float2 xc[8], xn[8];
    auto ldA = [&](float2* d, int kb) {
        const int k = kb * 16 + 2 * tg;
        d[0] = *(const float2*)(Xr + k);
        d[1] = *(const float2*)(Xr + 8 * D_DIM + k);
        d[2] = *(const float2*)(Xr + k + 8);
        d[3] = *(const float2*)(Xr + 8 * D_DIM + k + 8);
        d[4] = *(const float2*)(Xr + 16 * D_DIM + k);
        d[5] = *(const float2*)(Xr + 24 * D_DIM + k);
        d[6] = *(const float2*)(Xr + 16 * D_DIM + k + 8);
        d[7] = *(const float2*)(Xr + 24 * D_DIM + k + 8);
    };
    ldB(bf0, 0);
    ldA(xc, 0);

    #pragma unroll 4
    for (int kb = 0; kb < 36; kb++) {
        uint4* cur = (kb & 1) ? bf1 : bf0;
        uint4* nxt = (kb & 1) ? bf0 : bf1;
        float2* xcur = (kb & 1) ? xn : xc;
        float2* xnxt = (kb & 1) ? xc : xn;
        if (kb < 35) { ldB(nxt, kb + 1); ldA(xnxt, kb + 1); }

        uint32_t a0[4], a1[4];
        a0[0] = packh2(xcur[0]); a0[1] = packh2(xcur[1]);
        a0[2] = packh2(xcur[2]); a0[3] = packh2(xcur[3]);
        a1[0] = packh2(xcur[4]); a1[1] = packh2(xcur[5]);
        a1[2] = packh2(xcur[6]); a1[3] = packh2(xcur[7]);

        #pragma unroll
        for (int p = 0; p < 2; p++) {
            mma_f16(acc[0][2 * p + 0], a0, cur[p].x, cur[p].y);
            mma_f16(acc[0][2 * p + 1], a0, cur[p].z, cur[p].w);
            mma_f16(acc[1][2 * p + 0], a1, cur[p].x, cur[p].y);
            mma_f16(acc[1][2 * p + 1], a1, cur[p].z, cur[p].w);
        }
    }

    __half* outb = isB ? (bprojh + (size_t)mloc * H1_DIM)
                       : (aprojh + (size_t)m0 * H1_DIM);
    #pragma unroll
    for (int mt = 0; mt < 2; mt++) {
        __half* orow0 = outb + (size_t)(mt * 16 + g) * H1_DIM;
        __half* orow1 = orow0 + 8 * H1_DIM;
        #pragma unroll
        for (int nt = 0; nt < 4; nt++) {
            const int j = j0 + nt * 8 + 2 * tg;
            const int sl = permslot(j);
            float v0 = acc[mt][nt][0], v1 = acc[mt][nt][1];
            float v2 = acc[mt][nt][2], v3 = acc[mt][nt][3];
            if (isB) {
                const float ba = b1[j], bb = b1[j + 1];
                v0 += ba; v1 += bb; v2 += ba; v3 += bb;
            }
            *(__half2*)&orow0[sl] = __floats2half2_rn(v0, v1);
            *(__half2*)&orow1[sl] = __floats2half2_rn(v2, v3);
        }
    }
}

// ============================================================================
// Main fused kernel (R12 + 128k stages: 4 stages, 3-ring, 4 barriers/tile)
//   CTA: 1 n x 64 m x 256 h2. 128 threads, 4 warps = 2 m-bands x 2 j-bands,
//   warp tile 32m x 128j. K=512 in 4 stages of 128. 2 CTAs/SM resident.
//   bp staging: 3-buffer cp.async ring (16KB/stage); stages 0,1 issued in
//   prologue; per stage: wait_group 1 -> one __syncthreads -> issue s+2.
//   B: LDG.128 of pre-fragmented W2, double-buffered in registers.
//   A: fragments = HADD2+HMAX2 from one LDS.64 per source (k-permuted).
// ============================================================================
__global__ __launch_bounds__(128, 2) void pair_mlp_main(
    const __half* __restrict__ aprojh, const __half* __restrict__ bprojh,
    const uint4* __restrict__ w2f, const float* __restrict__ b2,
    const float* __restrict__ w3, const float* __restrict__ b3,
    float* __restrict__ out)
{
    __shared__ __align__(16) __half s_arowh[H1_DIM];
    __shared__ float s_b2[H2_DIM];
    __shared__ float s_w3[H2_DIM];
    __shared__ float s_part[64 * 2];
    __shared__ __align__(16) __half s_bp[3][64][136];  // 128 data halves + pad

    const int tid = threadIdx.x;
    const int wid = tid >> 5;
    const int lid = tid & 31;
    const int wr  = wid >> 1;   // m band: rows wr*32 (0..1)
    const int wc  = wid & 1;    // j band: cols wc*128
    const int g   = lid >> 2;
    const int tg  = lid & 3;

    const int t  = blockIdx.x;            // 0..8191
    const int b  = t >> 12;
    const int n  = (t >> 2) & (N_DIM - 1);
    const int m0 = (t & 3) * 64;

    const __half* bpg = bprojh + (size_t)(b * M_DIM + m0) * H1_DIM;

    // cp.async: stage s of bproj fp16 (64 rows x 128 halves) into s_bp[s%3]
    auto issue_bp = [&](int s) {
        if (s < 4) {
            const int buf = s % 3;
            const int kc = s * 128;
            #pragma unroll
            for (int i = 0; i < 8; i++) {
                int idx = tid + i * 128;           // 0..1023
                int row = idx >> 4, c = idx & 15;  // 16 x 16B per row
                cp16(smem_to_u32(&s_bp[buf][row][c * 8]),
                     bpg + (size_t)row * H1_DIM + kc + c * 8);
            }
        }
        cp_commit();
    };
    issue_bp(0);
    issue_bp(1);

    // arow: 512 halves = 128 x uint2 (k-permuted in GMEM)
    ((uint2*)s_arowh)[tid] =
        ((const uint2*)(aprojh + (size_t)(b * N_DIM + n) * H1_DIM))[tid];
    s_b2[tid] = b2[tid];         s_b2[tid + 128] = b2[tid + 128];
    s_w3[tid] = w3[tid];         s_w3[tid + 128] = w3[tid + 128];

    float acc[2][16][4];
    #pragma unroll
    for (int mt = 0; mt < 2; mt++)
        #pragma unroll
        for (int nt = 0; nt < 16; nt++)
            #pragma unroll
            for (int q = 0; q < 4; q++) acc[mt][nt][q] = 0.0f;

    const int r0 = wr * 32 + g;   // warp rows: r0, r0+8, r0+16, r0+24

    // B-fragment register double buffer, prefetched by global k16-slice kb
    uint4 bfa[8], bfb[8];
    auto ldB = [&](uint4* dst, int kb) {
        const int fb = (kb * 16 + wc * 8) * 32 + lid;
        #pragma unroll
        for (int p = 0; p < 8; p++) dst[p] = w2f[fb + p * 32];
    };
    ldB(bfa, 0);

    for (int s = 0; s < 4; s++) {
        asm volatile("cp.async.wait_group 1;" ::: "memory");
        __syncthreads();          // stage s visible; all warps done with s-1
        issue_bp(s + 2);          // (s+2)%3 buffer last read at stage s-1

        const int buf = s % 3;
        #pragma unroll
        for (int kk = 0; kk < 8; kk++) {
            const int kb = s * 8 + kk;
            uint4* cur = (kb & 1) ? bfb : bfa;
            uint4* nxt = (kb & 1) ? bfa : bfb;
            if (kb < 31) ldB(nxt, kb + 1);         // prefetch next k16 slice

            // ---- A fragments (k-permuted): one LDS.64 per source ----
            const int ko = kk * 16 + tg * 4;       // col within the 128-half stage
            const uint2 ua = *(const uint2*)&s_arowh[s * 128 + ko];
            const uint2 u0 = *(const uint2*)&s_bp[buf][r0     ][ko];
            const uint2 u1 = *(const uint2*)&s_bp[buf][r0 +  8][ko];
            const uint2 u2 = *(const uint2*)&s_bp[buf][r0 + 16][ko];
            const uint2 u3 = *(const uint2*)&s_bp[buf][r0 + 24][ko];
            uint32_t a0[4], a1[4];
            a0[0] = fragAB(ua.x, u0.x);
            a0[1] = fragAB(ua.x, u1.x);
            a0[2] = fragAB(ua.y, u0.y);
            a0[3] = fragAB(ua.y, u1.y);
            a1[0] = fragAB(ua.x, u2.x);
            a1[1] = fragAB(ua.x, u3.x);
            a1[2] = fragAB(ua.y, u2.y);
            a1[3] = fragAB(ua.y, u3.y);

            // ---- 32 MMAs on the current B slice ----
            #pragma unroll
            for (int p = 0; p < 8; p++) {
                mma_f16(acc[0][2 * p + 0], a0, cur[p].x, cur[p].y);
                mma_f16(acc[0][2 * p + 1], a0, cur[p].z, cur[p].w);
                mma_f16(acc[1][2 * p + 0], a1, cur[p].x, cur[p].y);
                mma_f16(acc[1][2 * p + 1], a1, cur[p].z, cur[p].w);
            }
        }
    }

    // ---- epilogue: out[row] = sum_j relu(D[row,j]+b2[j])*w3[j] + b3 ----
    float p0 = 0.0f, p1 = 0.0f, p2s = 0.0f, p3s = 0.0f;  // rows r0,+8,+16,+24
    #pragma unroll
    for (int nt = 0; nt < 16; nt++) {
        const int j = wc * 128 + nt * 8 + 2 * tg;
        const float b2a = s_b2[j], b2b = s_b2[j + 1];
        const float w3a = s_w3[j], w3b = s_w3[j + 1];
        const float* c0 = acc[0][nt];
        const float* c1 = acc[1][nt];
        p0  += fmaxf(c0[0] + b2a, 0.0f) * w3a + fmaxf(c0[1] + b2b, 0.0f) * w3b;
        p1  += fmaxf(c0[2] + b2a, 0.0f) * w3a + fmaxf(c0[3] + b2b, 0.0f) * w3b;
        p2s += fmaxf(c1[0] + b2a, 0.0f) * w3a + fmaxf(c1[1] + b2b, 0.0f) * w3b;
        p3s += fmaxf(c1[2] + b2a, 0.0f) * w3a + fmaxf(c1[3] + b2b, 0.0f) * w3b;
    }
    #pragma unroll
    for (int off = 1; off < 4; off <<= 1) {
        p0  += __shfl_xor_sync(0xffffffffu, p0, off);
        p1  += __shfl_xor_sync(0xffffffffu, p1, off);
        p2s += __shfl_xor_sync(0xffffffffu, p2s, off);
        p3s += __shfl_xor_sync(0xffffffffu, p3s, off);
    }

    __syncthreads();
    if (tg == 0) {
        s_part[(r0     ) * 2 + wc] = p0;
        s_part[(r0 +  8) * 2 + wc] = p1;
        s_part[(r0 + 16) * 2 + wc] = p2s;
        s_part[(r0 + 24) * 2 + wc] = p3s;
    }
    __syncthreads();
    if (tid < 64) {
        float v = s_part[tid * 2 + 0] + s_part[tid * 2 + 1] + b3[0];
        out[(size_t)(b * N_DIM + n) * M_DIM + m0 + tid] = v;
    }
}

// ============================================================================
// Launch
// ============================================================================
extern "C" void kernel_launch(void* const* d_in, const int* in_sizes, int n_in,
                              void* d_out, int out_size) {
    const float* PhiA = (const float*)d_in[0];
    const float* PhiB = (const float*)d_in[1];
    const float* W1a  = (const float*)d_in[2];
    const float* W1b  = (const float*)d_in[3];
    const float* b1   = (const float*)d_in[4];
    const float* W2   = (const float*)d_in[5];
    const float* b2   = (const float*)d_in[6];
    const float* W3   = (const float*)d_in[7];
    const float* b3   = (const float*)d_in[8];
    float* out = (float*)d_out;

    __half* aprojh = nullptr;
    __half* bprojh = nullptr;
    uint4 *w2f = nullptr, *w1af = nullptr, *w1bf = nullptr;
    cudaGetSymbolAddress((void**)&aprojh, g_aprojh);
    cudaGetSymbolAddress((void**)&bprojh, g_bprojh);
    cudaGetSymbolAddress((void**)&w2f, g_w2frag);
    cudaGetSymbolAddress((void**)&w1af, g_w1afrag);
    cudaGetSymbolAddress((void**)&w1bf, g_w1bfrag);

    // fragment all weight matrices (W2, W1a, W1b)
    wfrag_kernel<<<dim3(36, 32, 3), 32>>>(W2, W1a, W1b, w2f, w1af, w1bf);
    // tensor-core projections -> k-permuted fp16 aproj/bproj
    proj_mma_kernel<<<dim3((B_DIM * N_DIM + B_DIM * M_DIM) / 32, H1_DIM / 128), 128>>>(
        PhiA, PhiB, b1, w1af, w1bf, aprojh, bprojh);
    // fused pairwise MLP
    pair_mlp_main<<<B_DIM * N_DIM * (M_DIM / 64), 128>>>(
        aprojh, bprojh, w2f, b2, W3, b3, out);
}

// round 14
// speedup vs baseline: 1.1100x; 1.1100x over previous
#include <cuda_runtime.h>
#include <cuda_fp16.h>
#include <cstdint>

// ============================================================================
// Problem constants
// ============================================================================
#define B_DIM  2
#define N_DIM  1024
#define M_DIM  256
#define D_DIM  576
#define H1_DIM 512
#define H2_DIM 256

// Scratch (allocation-free rule: __device__ globals)
// aprojh / bprojh are stored K-PERMUTED: within each 16-column block, the
// half2 pair for logical k-pair p (pairs 0..7) lives at slot (p&3)*2+(p>>2).
// Each mma-lane's two half2s (k0,k0+1),(k0+8,k0+9) are then one LDS.64.
__device__ __half g_aprojh[B_DIM * N_DIM * H1_DIM];   // fp16(a_proj), k-permuted
__device__ __half g_bprojh[B_DIM * M_DIM * H1_DIM];   // fp16(b_proj + b1), k-permuted
__device__ uint4  g_w2frag[32 * 16 * 32];             // W2  pre-packed mma B-fragments
__device__ uint4  g_w1afrag[36 * 32 * 32];            // W1a pre-packed mma B-fragments
__device__ uint4  g_w1bfrag[36 * 32 * 32];            // W1b pre-packed mma B-fragments

// storage half-index of the pair starting at even logical column c
__host__ __device__ __forceinline__ int permslot(int c) {
    int p = (c & 15) >> 1;
    return (c & ~15) + (((p & 3) * 2 + (p >> 2)) << 1);
}

// ============================================================================
// PTX helpers (base ISA — harness compiles for compute_103, no 'a' features)
// ============================================================================
__device__ __forceinline__ uint32_t smem_to_u32(const void* p) {
    uint32_t a;
    asm("{ .reg .u64 t; cvta.to.shared.u64 t, %1; cvt.u32.u64 %0, t; }" : "=r"(a) : "l"(p));
    return a;
}

__device__ __forceinline__ void cp16(uint32_t s, const void* g) {
    asm volatile("cp.async.cg.shared.global [%0], [%1], 16;" :: "r"(s), "l"(g) : "memory");
}
__device__ __forceinline__ void cp_commit() {
    asm volatile("cp.async.commit_group;" ::: "memory");
}

__device__ __forceinline__ void mma_f16(float* c, const uint32_t* a, uint32_t b0, uint32_t b1) {
    asm volatile(
        "mma.sync.aligned.m16n8k16.row.col.f32.f16.f16.f32 "
        "{%0,%1,%2,%3}, {%4,%5,%6,%7}, {%8,%9}, {%0,%1,%2,%3};"
        : "+f"(c[0]), "+f"(c[1]), "+f"(c[2]), "+f"(c[3])
        : "r"(a[0]), "r"(a[1]), "r"(a[2]), "r"(a[3]), "r"(b0), "r"(b1));
}

// h1 fragment: fp16 relu(a + b), 2 ops (HADD2 + HMAX2)
__device__ __forceinline__ uint32_t fragAB(uint32_t a, uint32_t b) {
    __half2 z = __float2half2_rn(0.0f);
    __half2 h = __hmax2(__hadd2(*(__half2*)&a, *(__half2*)&b), z);
    return *(uint32_t*)&h;
}

__device__ __forceinline__ uint32_t packh2(float2 v) {
    __half2 h = __floats2half2_rn(v.x, v.y);
    return *(uint32_t*)&h;
}

// ============================================================================
// Prep A: fragment ALL weight matrices into mma B-operand layout (fp16).
// ============================================================================
__global__ void wfrag_kernel(
    const float* __restrict__ W2, const float* __restrict__ W1a,
    const float* __restrict__ W1b,
    uint4* __restrict__ w2f, uint4* __restrict__ w1af, uint4* __restrict__ w1bf)
{
    const int kb = blockIdx.x, jbp = blockIdx.y, z = blockIdx.z;
    const int lid = threadIdx.x;
    const float* W;
    uint4* out;
    int stride, outidx;
    if (z == 0) {
        if (kb >= 32 || jbp >= 16) return;
        W = W2; out = w2f; stride = H2_DIM;
        outidx = (kb * 16 + jbp) * 32 + lid;
    } else {
        W = (z == 1) ? W1a : W1b;
        out = (z == 1) ? w1af : w1bf;
        stride = H1_DIM;
        outidx = (kb * 32 + jbp) * 32 + lid;
    }
    const int gg = lid >> 2, tg = lid & 3;
    const int k0 = kb * 16 + 2 * tg;
    const int j0 = jbp * 16 + gg;

    auto p2 = [&](int k, int j) {
        __half2 h = __floats2half2_rn(W[(size_t)k * stride + j],
                                      W[(size_t)(k + 1) * stride + j]);
        return *(uint32_t*)&h;
    };
    uint4 u;
    u.x = p2(k0, j0);
    u.y = p2(k0 + 8, j0);
    u.z = p2(k0, j0 + 8);
    u.w = p2(k0 + 8, j0 + 8);
    out[outidx] = u;
}

// ============================================================================
// Prep B: projection GEMMs on tensor cores.
// ============================================================================
__global__ __launch_bounds__(128) void proj_mma_kernel(
    const float* __restrict__ PhiA, const float* __restrict__ PhiB,
    const float* __restrict__ b1,
    const uint4* __restrict__ w1af, const uint4* __restrict__ w1bf,
    __half* __restrict__ aprojh, __half* __restrict__ bprojh)
{
    const int tid = threadIdx.x;
    const int wid = tid >> 5, lid = tid & 31;
    const int g = lid >> 2, tg = lid & 3;
    const int m0 = blockIdx.x * 32;
    const bool isB = m0 >= (B_DIM * N_DIM);
    const float* X = isB ? PhiB : PhiA;
    const int mloc = isB ? m0 - B_DIM * N_DIM : m0;
    const uint4* wf = isB ? w1bf : w1af;
    const int j0 = blockIdx.y * 128 + wid * 32;
    const int jbp0 = j0 >> 4;

    const float* Xr = X + (size_t)(mloc + g) * D_DIM;

    float acc[2][4][4] = {};

    uint4 bf0[2], bf1[2];
    auto ldB = [&](uint4* d, int kb) {
        const int fb = (kb * 32 + jbp0) * 32 + lid;
        d[0] = wf[fb];
        d[1] = wf[fb + 32];
    };
    float2 xc[8], xn[8];
    auto ldA = [&](float2* d, int kb) {
        const int k = kb * 16 + 2 * tg;
        d[0] = *(const float2*)(Xr + k);
        d[1] = *(const float2*)(Xr + 8 * D_DIM + k);
        d[2] = *(const float2*)(Xr + k + 8);
        d[3] = *(const float2*)(Xr + 8 * D_DIM + k + 8);
        d[4] = *(const float2*)(Xr + 16 * D_DIM + k);
        d[5] = *(const float2*)(Xr + 24 * D_DIM + k);
        d[6] = *(const float2*)(Xr + 16 * D_DIM + k + 8);
        d[7] = *(const float2*)(Xr + 24 * D_DIM + k + 8);
    };
    ldB(bf0, 0);
    ldA(xc, 0);

    #pragma unroll 4
    for (int kb = 0; kb < 36; kb++) {
        uint4* cur = (kb & 1) ? bf1 : bf0;
        uint4* nxt = (kb & 1) ? bf0 : bf1;
        float2* xcur = (kb & 1) ? xn : xc;
        float2* xnxt = (kb & 1) ? xc : xn;
        if (kb < 35) { ldB(nxt, kb + 1); ldA(xnxt, kb + 1); }

        uint32_t a0[4], a1[4];
        a0[0] = packh2(xcur[0]); a0[1] = packh2(xcur[1]);
        a0[2] = packh2(xcur[2]); a0[3] = packh2(xcur[3]);
        a1[0] = packh2(xcur[4]); a1[1] = packh2(xcur[5]);
        a1[2] = packh2(xcur[6]); a1[3] = packh2(xcur[7]);

        #pragma unroll
        for (int p = 0; p < 2; p++) {
            mma_f16(acc[0][2 * p + 0], a0, cur[p].x, cur[p].y);
            mma_f16(acc[0][2 * p + 1], a0, cur[p].z, cur[p].w);
            mma_f16(acc[1][2 * p + 0], a1, cur[p].x, cur[p].y);
            mma_f16(acc[1][2 * p + 1], a1, cur[p].z, cur[p].w);
        }
    }

    __half* outb = isB ? (bprojh + (size_t)mloc * H1_DIM)
                       : (aprojh + (size_t)m0 * H1_DIM);
    #pragma unroll
    for (int mt = 0; mt < 2; mt++) {
        __half* orow0 = outb + (size_t)(mt * 16 + g) * H1_DIM;
        __half* orow1 = orow0 + 8 * H1_DIM;
        #pragma unroll
        for (int nt = 0; nt < 4; nt++) {
            const int j = j0 + nt * 8 + 2 * tg;
            const int sl = permslot(j);
            float v0 = acc[mt][nt][0], v1 = acc[mt][nt][1];
            float v2 = acc[mt][nt][2], v3 = acc[mt][nt][3];
            if (isB) {
                const float ba = b1[j], bb = b1[j + 1];
                v0 += ba; v1 += bb; v2 += ba; v3 += bb;
            }
            *(__half2*)&orow0[sl] = __floats2half2_rn(v0, v1);
            *(__half2*)&orow1[sl] = __floats2half2_rn(v2, v3);
        }
    }
}

// ============================================================================
// Main fused kernel — 4n x 64m tiles, bp slab resident in smem.
//   Grid 2048, 128 threads, 4 warps = 2 m-bands x 2 j-bands, 2 CTAs/SM.
//   Per tile: cp.async the FULL bp slab (64 rows x 512 k, stride-80 stages)
//   + 4 arows ONCE, then 4 sequential GEMM passes (one per n) with ZERO
//   barriers / cp.async in the K-loop. B-frag prefetch chains across pass
//   boundaries (kb==31 prefetches kb=0 for the next pass).
//   Smem layout (dynamic, ~88.5 KB):
//     [0)        s_bp   : 8 stages x 64 rows x 80 halves   (81920 B)
//     [81920)    s_arow : 4 x 512 halves                   (4096 B)
//     [86016)    s_b2   : 256 f32                          (1024 B)
//     [87040)    s_w3   : 256 f32                          (1024 B)
//     [88064)    s_part : 128 f32                          (512 B)
// ============================================================================
#define SM_BP    0
#define SM_AROW  81920
#define SM_B2    86016
#define SM_W3    87040
#define SM_PART  88064
#define SMEM_MAIN (88064 + 512)

__global__ __launch_bounds__(128, 2) void pair_mlp_main(
    const __half* __restrict__ aprojh, const __half* __restrict__ bprojh,
    const uint4* __restrict__ w2f, const float* __restrict__ b2,
    const float* __restrict__ w3, const float* __restrict__ b3,
    float* __restrict__ out)
{
    extern __shared__ __align__(16) char smem[];
    __half* s_bp   = (__half*)(smem + SM_BP);    // [stage][row][80]
    __half* s_arow = (__half*)(smem + SM_AROW);  // [4][512]
    float*  s_b2   = (float*)(smem + SM_B2);
    float*  s_w3   = (float*)(smem + SM_W3);
    float*  s_part = (float*)(smem + SM_PART);

    const int tid = threadIdx.x;
    const int wid = tid >> 5;
    const int lid = tid & 31;
    const int wr  = wid >> 1;   // m band: rows wr*32 (0..1)
    const int wc  = wid & 1;    // j band: cols wc*128
    const int g   = lid >> 2;
    const int tg  = lid & 3;

    const int T  = blockIdx.x;            // 0..2047
    const int ng = T >> 2;                // n-group (4 n each), 0..511
    const int m0 = (T & 3) * 64;
    const int n0g = ng * 4;               // global n row 0..2044 (within b*N+n space)
    const int b  = n0g >> 10;             // batch
    // bp rows for this (b, m0)
    const __half* bpg = bprojh + (size_t)(b * M_DIM + m0) * H1_DIM;
    const __half* apg = aprojh + (size_t)n0g * H1_DIM;

    // ---- cp.async: full bp slab (64 rows x 512 halves -> 8 stages x 80) ----
    {
        const uint32_t sb = smem_to_u32(s_bp);
        #pragma unroll
        for (int i = 0; i < 32; i++) {
            int idx = tid + i * 128;              // 0..4095
            int st  = idx >> 9;                   // 8 chunks x 64 rows per stage
            int row = (idx >> 3) & 63;
            int c   = idx & 7;
            cp16(sb + st * 10240 + row * 160 + c * 16,
                 bpg + (size_t)row * H1_DIM + st * 64 + c * 8);
        }
        // 4 arows (4 x 1024 B)
        const uint32_t sa = smem_to_u32(s_arow);
        #pragma unroll
        for (int i = 0; i < 2; i++) {
            int idx = tid + i * 128;              // 0..255
            int p = idx >> 6, c = idx & 63;
            cp16(sa + p * 1024 + c * 16, apg + (size_t)p * H1_DIM + c * 8);
        }
        cp_commit();
    }
    s_b2[tid] = b2[tid];   s_b2[tid + 128] = b2[tid + 128];
    s_w3[tid] = w3[tid];   s_w3[tid + 128] = w3[tid + 128];

    const int r0 = wr * 32 + g;   // warp rows: r0, r0+8, r0+16, r0+24

    // B-fragment register double buffer, prefetched by k16-slice kb
    uint4 bfa[8], bfb[8];
    auto ldB = [&](uint4* dst, int kb) {
        const int fb = (kb * 16 + wc * 8) * 32 + lid;
        #pragma unroll
        for (int p = 0; p < 8; p++) dst[p] = w2f[fb + p * 32];
    };
    ldB(bfa, 0);

    asm volatile("cp.async.wait_group 0;" ::: "memory");
    __syncthreads();

    for (int p = 0; p < 4; p++) {
        float acc[2][16][4];
        #pragma unroll
        for (int mt = 0; mt < 2; mt++)
            #pragma unroll
            for (int nt = 0; nt < 16; nt++)
                #pragma unroll
                for (int q = 0; q < 4; q++) acc[mt][nt][q] = 0.0f;

        const __half* ar = s_arow + p * 512;

        #pragma unroll 8
        for (int kb = 0; kb < 32; kb++) {
            uint4* cur = (kb & 1) ? bfb : bfa;
            uint4* nxt = (kb & 1) ? bfa : bfb;
            // prefetch next slice; at kb==31 prefetch kb=0 for the next pass
            ldB(nxt, (kb < 31) ? kb + 1 : 0);

            // ---- A fragments (k-permuted): one LDS.64 per source ----
            const int st = kb >> 2;
            const int ko = (kb & 3) * 16 + tg * 4;     // within-stage column
            const __half* bps = s_bp + st * 5120 + ko; // stage base + col
            const uint2 ua = *(const uint2*)&ar[kb * 16 + tg * 4];
            const uint2 u0 = *(const uint2*)&bps[(r0     ) * 80];
            const uint2 u1 = *(const uint2*)&bps[(r0 +  8) * 80];
            const uint2 u2 = *(const uint2*)&bps[(r0 + 16) * 80];
            const uint2 u3 = *(const uint2*)&bps[(r0 + 24) * 80];
            uint32_t a0[4], a1[4];
            a0[0] = fragAB(ua.x, u0.x);
            a0[1] = fragAB(ua.x, u1.x);
            a0[2] = fragAB(ua.y, u0.y);
            a0[3] = fragAB(ua.y, u1.y);
            a1[0] = fragAB(ua.x, u2.x);
            a1[1] = fragAB(ua.x, u3.x);
            a1[2] = fragAB(ua.y, u2.y);
            a1[3] = fragAB(ua.y, u3.y);

            // ---- 32 MMAs on the current B slice ----
            #pragma unroll
            for (int q = 0; q < 8; q++) {
                mma_f16(acc[0][2 * q + 0], a0, cur[q].x, cur[q].y);
                mma_f16(acc[0][2 * q + 1], a0, cur[q].z, cur[q].w);
                mma_f16(acc[1][2 * q + 0], a1, cur[q].x, cur[q].y);
                mma_f16(acc[1][2 * q + 1], a1, cur[q].z, cur[q].w);
            }
        }

        // ---- epilogue pass p: out[n0g+p, m0+row] ----
        float p0 = 0.0f, p1 = 0.0f, p2s = 0.0f, p3s = 0.0f;
        #pragma unroll
        for (int nt = 0; nt < 16; nt++) {
            const int j = wc * 128 + nt * 8 + 2 * tg;
            const float b2a = s_b2[j], b2b = s_b2[j + 1];
            const float w3a = s_w3[j], w3b = s_w3[j + 1];
            const float* c0 = acc[0][nt];
            const float* c1 = acc[1][nt];
            p0  += fmaxf(c0[0] + b2a, 0.0f) * w3a + fmaxf(c0[1] + b2b, 0.0f) * w3b;
            p1  += fmaxf(c0[2] + b2a, 0.0f) * w3a + fmaxf(c0[3] + b2b, 0.0f) * w3b;
            p2s += fmaxf(c1[0] + b2a, 0.0f) * w3a + fmaxf(c1[1] + b2b, 0.0f) * w3b;
            p3s += fmaxf(c1[2] + b2a, 0.0f) * w3a + fmaxf(c1[3] + b2b, 0.0f) * w3b;
        }
        #pragma unroll
        for (int off = 1; off < 4; off <<= 1) {
            p0  += __shfl_xor_sync(0xffffffffu, p0, off);
            p1  += __shfl_xor_sync(0xffffffffu, p1, off);
            p2s += __shfl_xor_sync(0xffffffffu, p2s, off);
            p3s += __shfl_xor_sync(0xffffffffu, p3s, off);
        }

        __syncthreads();   // previous pass's s_part reads complete
        if (tg == 0) {
            s_part[(r0     ) * 2 + wc] = p0;
            s_part[(r0 +  8) * 2 + wc] = p1;
            s_part[(r0 + 16) * 2 + wc] = p2s;
            s_part[(r0 + 24) * 2 + wc] = p3s;
        }
        __syncthreads();
        if (tid < 64) {
            float v = s_part[tid * 2 + 0] + s_part[tid * 2 + 1] + b3[0];
            out[(size_t)(n0g + p) * M_DIM + m0 + tid] = v;
        }
    }
}

// ============================================================================
// Launch
// ============================================================================
extern "C" void kernel_launch(void* const* d_in, const int* in_sizes, int n_in,
                              void* d_out, int out_size) {
    const float* PhiA = (const float*)d_in[0];
    const float* PhiB = (const float*)d_in[1];
    const float* W1a  = (const float*)d_in[2];
    const float* W1b  = (const float*)d_in[3];
    const float* b1   = (const float*)d_in[4];
    const float* W2   = (const float*)d_in[5];
    const float* b2   = (const float*)d_in[6];
    const float* W3   = (const float*)d_in[7];
    const float* b3   = (const float*)d_in[8];
    float* out = (float*)d_out;

    __half* aprojh = nullptr;
    __half* bprojh = nullptr;
    uint4 *w2f = nullptr, *w1af = nullptr, *w1bf = nullptr;
    cudaGetSymbolAddress((void**)&aprojh, g_aprojh);
    cudaGetSymbolAddress((void**)&bprojh, g_bprojh);
    cudaGetSymbolAddress((void**)&w2f, g_w2frag);
    cudaGetSymbolAddress((void**)&w1af, g_w1afrag);
    cudaGetSymbolAddress((void**)&w1bf, g_w1bfrag);

    // fragment all weight matrices (W2, W1a, W1b)
    wfrag_kernel<<<dim3(36, 32, 3), 32>>>(W2, W1a, W1b, w2f, w1af, w1bf);
    // tensor-core projections -> k-permuted fp16 aproj/bproj
    proj_mma_kernel<<<dim3((B_DIM * N_DIM + B_DIM * M_DIM) / 32, H1_DIM / 128), 128>>>(
        PhiA, PhiB, b1, w1af, w1bf, aprojh, bprojh);
    // fused pairwise MLP (4n x 64m tiles, resident bp slab)
    cudaFuncSetAttribute(pair_mlp_main, cudaFuncAttributeMaxDynamicSharedMemorySize,
                         SMEM_MAIN);
    pair_mlp_main<<<B_DIM * N_DIM * M_DIM / (4 * 64), 128, SMEM_MAIN>>>(
        aprojh, bprojh, w2f, b2, W3, b3, out);
}

// round 15
// speedup vs baseline: 1.1106x; 1.0006x over previous
#include <cuda_runtime.h>
#include <cuda_fp16.h>
#include <cstdint>

// ============================================================================
// Problem constants
// ============================================================================
#define B_DIM  2
#define N_DIM  1024
#define M_DIM  256
#define D_DIM  576
#define H1_DIM 512
#define H2_DIM 256

// Scratch (allocation-free rule: __device__ globals)
// aprojh / bprojh are stored K-PERMUTED: within each 16-column block, the
// half2 pair for logical k-pair p (pairs 0..7) lives at slot (p&3)*2+(p>>2).
// Each mma-lane's two half2s (k0,k0+1),(k0+8,k0+9) are then one LDS.64.
__device__ __half g_aprojh[B_DIM * N_DIM * H1_DIM];   // fp16(a_proj), k-permuted
__device__ __half g_bprojh[B_DIM * M_DIM * H1_DIM];   // fp16(b_proj + b1), k-permuted
__device__ uint4  g_w2frag[32 * 16 * 32];             // W2  pre-packed mma B-fragments
__device__ uint4  g_w1afrag[36 * 32 * 32];            // W1a pre-packed mma B-fragments
__device__ uint4  g_w1bfrag[36 * 32 * 32];            // W1b pre-packed mma B-fragments

// storage half-index of the pair starting at even logical column c
__host__ __device__ __forceinline__ int permslot(int c) {
    int p = (c & 15) >> 1;
    return (c & ~15) + (((p & 3) * 2 + (p >> 2)) << 1);
}

// ============================================================================
// PTX helpers (base ISA — harness compiles for compute_103, no 'a' features)
// ============================================================================
__device__ __forceinline__ uint32_t smem_to_u32(const void* p) {
    uint32_t a;
    asm("{ .reg .u64 t; cvta.to.shared.u64 t, %1; cvt.u32.u64 %0, t; }" : "=r"(a) : "l"(p));
    return a;
}

__device__ __forceinline__ void cp16(uint32_t s, const void* g) {
    asm volatile("cp.async.cg.shared.global [%0], [%1], 16;" :: "r"(s), "l"(g) : "memory");
}
__device__ __forceinline__ void cp_commit() {
    asm volatile("cp.async.commit_group;" ::: "memory");
}

__device__ __forceinline__ void mma_f16(float* c, const uint32_t* a, uint32_t b0, uint32_t b1) {
    asm volatile(
        "mma.sync.aligned.m16n8k16.row.col.f32.f16.f16.f32 "
        "{%0,%1,%2,%3}, {%4,%5,%6,%7}, {%8,%9}, {%0,%1,%2,%3};"
        : "+f"(c[0]), "+f"(c[1]), "+f"(c[2]), "+f"(c[3])
        : "r"(a[0]), "r"(a[1]), "r"(a[2]), "r"(a[3]), "r"(b0), "r"(b1));
}

// h1 fragment: fp16 relu(a + b), 2 ops (HADD2 + HMAX2)
__device__ __forceinline__ uint32_t fragAB(uint32_t a, uint32_t b) {
    __half2 z = __float2half2_rn(0.0f);
    __half2 h = __hmax2(__hadd2(*(__half2*)&a, *(__half2*)&b), z);
    return *(uint32_t*)&h;
}

__device__ __forceinline__ uint32_t packh2(float2 v) {
    __half2 h = __floats2half2_rn(v.x, v.y);
    return *(uint32_t*)&h;
}

// ============================================================================
// Prep A: fragment ALL weight matrices into mma B-operand layout (fp16).
// 128 threads = 4 warps, each warp handles one jbp. Grid (36, 8, 3).
//   z=0: W2  [512][256] -> w2f  (kb<32, jbp<16)
//   z=1: W1a [576][512] -> w1af   z=2: W1b [576][512] -> w1bf
// ============================================================================
__global__ __launch_bounds__(128) void wfrag_kernel(
    const float* __restrict__ W2, const float* __restrict__ W1a,
    const float* __restrict__ W1b,
    uint4* __restrict__ w2f, uint4* __restrict__ w1af, uint4* __restrict__ w1bf)
{
    const int kb = blockIdx.x, z = blockIdx.z;
    const int wid = threadIdx.x >> 5;
    const int jbp = blockIdx.y * 4 + wid;
    const int lid = threadIdx.x & 31;
    const float* W;
    uint4* out;
    int stride, outidx;
    if (z == 0) {
        if (kb >= 32 || jbp >= 16) return;
        W = W2; out = w2f; stride = H2_DIM;
        outidx = (kb * 16 + jbp) * 32 + lid;
    } else {
        W = (z == 1) ? W1a : W1b;
        out = (z == 1) ? w1af : w1bf;
        stride = H1_DIM;
        outidx = (kb * 32 + jbp) * 32 + lid;
    }
    const int gg = lid >> 2, tg = lid & 3;
    const int k0 = kb * 16 + 2 * tg;
    const int j0 = jbp * 16 + gg;

    auto p2 = [&](int k, int j) {
        __half2 h = __floats2half2_rn(W[(size_t)k * stride + j],
                                      W[(size_t)(k + 1) * stride + j]);
        return *(uint32_t*)&h;
    };
    uint4 u;
    u.x = p2(k0, j0);
    u.y = p2(k0 + 8, j0);
    u.z = p2(k0, j0 + 8);
    u.w = p2(k0 + 8, j0 + 8);
    out[outidx] = u;
}

// ============================================================================
// Prep B: projection GEMMs on tensor cores, 3-deep register pipeline
// (DRAM latency on Phi loads was the binding cost at depth 1).
// ============================================================================
__global__ __launch_bounds__(128) void proj_mma_kernel(
    const float* __restrict__ PhiA, const float* __restrict__ PhiB,
    const float* __restrict__ b1,
    const uint4* __restrict__ w1af, const uint4* __restrict__ w1bf,
    __half* __restrict__ aprojh, __half* __restrict__ bprojh)
{
    const int tid = threadIdx.x;
    const int wid = tid >> 5, lid = tid & 31;
    const int g = lid >> 2, tg = lid & 3;
    const int m0 = blockIdx.x * 32;
    const bool isB = m0 >= (B_DIM * N_DIM);
    const float* X = isB ? PhiB : PhiA;
    const int mloc = isB ? m0 - B_DIM * N_DIM : m0;
    const uint4* wf = isB ? w1bf : w1af;
    const int j0 = blockIdx.y * 128 + wid * 32;
    const int jbp0 = j0 >> 4;

    const float* Xr = X + (size_t)(mloc + g) * D_DIM;

    float acc[2][4][4] = {};

    uint4 bf[3][2];
    auto ldB = [&](uint4* d, int kb) {
        const int fb = (kb * 32 + jbp0) * 32 + lid;
        d[0] = wf[fb];
        d[1] = wf[fb + 32];
    };
    float2 x[3][8];
    auto ldA = [&](float2* d, int kb) {
        const int k = kb * 16 + 2 * tg;
        d[0] = *(const float2*)(Xr + k);
        d[1] = *(const float2*)(Xr + 8 * D_DIM + k);
        d[2] = *(const float2*)(Xr + k + 8);
        d[3] = *(const float2*)(Xr + 8 * D_DIM + k + 8);
        d[4] = *(const float2*)(Xr + 16 * D_DIM + k);
        d[5] = *(const float2*)(Xr + 24 * D_DIM + k);
        d[6] = *(const float2*)(Xr + 16 * D_DIM + k + 8);
        d[7] = *(const float2*)(Xr + 24 * D_DIM + k + 8);
    };
    ldA(x[0], 0); ldB(bf[0], 0);
    ldA(x[1], 1); ldB(bf[1], 1);
    ldA(x[2], 2); ldB(bf[2], 2);

    #pragma unroll 6
    for (int kb = 0; kb < 36; kb++) {
        const int sl = kb % 3;
        uint32_t a0[4], a1[4];
        a0[0] = packh2(x[sl][0]); a0[1] = packh2(x[sl][1]);
        a0[2] = packh2(x[sl][2]); a0[3] = packh2(x[sl][3]);
        a1[0] = packh2(x[sl][4]); a1[1] = packh2(x[sl][5]);
        a1[2] = packh2(x[sl][6]); a1[3] = packh2(x[sl][7]);
        uint4 c0 = bf[sl][0], c1 = bf[sl][1];

        if (kb < 33) { ldA(x[sl], kb + 3); ldB(bf[sl], kb + 3); }

        mma_f16(acc[0][0], a0, c0.x, c0.y);
        mma_f16(acc[0][1], a0, c0.z, c0.w);
        mma_f16(acc[1][0], a1, c0.x, c0.y);
        mma_f16(acc[1][1], a1, c0.z, c0.w);
        mma_f16(acc[0][2], a0, c1.x, c1.y);
        mma_f16(acc[0][3], a0, c1.z, c1.w);
        mma_f16(acc[1][2], a1, c1.x, c1.y);
        mma_f16(acc[1][3], a1, c1.z, c1.w);
    }

    __half* outb = isB ? (bprojh + (size_t)mloc * H1_DIM)
                       : (aprojh + (size_t)m0 * H1_DIM);
    #pragma unroll
    for (int mt = 0; mt < 2; mt++) {
        __half* orow0 = outb + (size_t)(mt * 16 + g) * H1_DIM;
        __half* orow1 = orow0 + 8 * H1_DIM;
        #pragma unroll
        for (int nt = 0; nt < 4; nt++) {
            const int j = j0 + nt * 8 + 2 * tg;
            const int sl = permslot(j);
            float v0 = acc[mt][nt][0], v1 = acc[mt][nt][1];
            float v2 = acc[mt][nt][2], v3 = acc[mt][nt][3];
            if (isB) {
                const float ba = b1[j], bb = b1[j + 1];
                v0 += ba; v1 += bb; v2 += ba; v3 += bb;
            }
            *(__half2*)&orow0[sl] = __floats2half2_rn(v0, v1);
            *(__half2*)&orow1[sl] = __floats2half2_rn(v2, v3);
        }
    }
}

// ============================================================================
// Main fused kernel — 4n x 64m tiles, bp slab resident in smem (R14 core).
//   Grid 2048, 128 threads, 4 warps = 2 m-bands x 2 j-bands, 2 CTAs/SM.
//   4 GEMM passes per tile, zero barriers/cp.async in the K-loop; epilogue
//   s_part double-buffered by pass parity -> ONE barrier per pass.
// ============================================================================
#define SM_BP    0
#define SM_AROW  81920
#define SM_B2    86016
#define SM_W3    87040
#define SM_PART  88064
#define SMEM_MAIN (88064 + 1024)

__global__ __launch_bounds__(128, 2) void pair_mlp_main(
    const __half* __restrict__ aprojh, const __half* __restrict__ bprojh,
    const uint4* __restrict__ w2f, const float* __restrict__ b2,
    const float* __restrict__ w3, const float* __restrict__ b3,
    float* __restrict__ out)
{
    extern __shared__ __align__(16) char smem[];
    __half* s_bp   = (__half*)(smem + SM_BP);    // [stage][row][80]
    __half* s_arow = (__half*)(smem + SM_AROW);  // [4][512]
    float*  s_b2   = (float*)(smem + SM_B2);
    float*  s_w3   = (float*)(smem + SM_W3);
    float*  s_part = (float*)(smem + SM_PART);   // [2][128] by pass parity

    const int tid = threadIdx.x;
    const int wid = tid >> 5;
    const int lid = tid & 31;
    const int wr  = wid >> 1;   // m band: rows wr*32 (0..1)
    const int wc  = wid & 1;    // j band: cols wc*128
    const int g   = lid >> 2;
    const int tg  = lid & 3;

    const int T  = blockIdx.x;            // 0..2047
    const int ng = T >> 2;                // n-group (4 n each), 0..511
    const int m0 = (T & 3) * 64;
    const int n0g = ng * 4;               // global row in (b*N+n) space
    const int b  = n0g >> 10;             // batch
    const __half* bpg = bprojh + (size_t)(b * M_DIM + m0) * H1_DIM;
    const __half* apg = aprojh + (size_t)n0g * H1_DIM;

    // ---- cp.async: full bp slab (64 rows x 512 halves -> 8 stages x 80) ----
    {
        const uint32_t sb = smem_to_u32(s_bp);
        #pragma unroll
        for (int i = 0; i < 32; i++) {
            int idx = tid + i * 128;              // 0..4095
            int st  = idx >> 9;
            int row = (idx >> 3) & 63;
            int c   = idx & 7;
            cp16(sb + st * 10240 + row * 160 + c * 16,
                 bpg + (size_t)row * H1_DIM + st * 64 + c * 8);
        }
        const uint32_t sa = smem_to_u32(s_arow);
        #pragma unroll
        for (int i = 0; i < 2; i++) {
            int idx = tid + i * 128;              // 0..255
            int p = idx >> 6, c = idx & 63;
            cp16(sa + p * 1024 + c * 16, apg + (size_t)p * H1_DIM + c * 8);
        }
        cp_commit();
    }
    s_b2[tid] = b2[tid];   s_b2[tid + 128] = b2[tid + 128];
    s_w3[tid] = w3[tid];   s_w3[tid + 128] = w3[tid + 128];

    const int r0 = wr * 32 + g;   // warp rows: r0, r0+8, r0+16, r0+24

    // B-fragment register double buffer, prefetched by k16-slice kb
    uint4 bfa[8], bfb[8];
    auto ldB = [&](uint4* dst, int kb) {
        const int fb = (kb * 16 + wc * 8) * 32 + lid;
        #pragma unroll
        for (int p = 0; p < 8; p++) dst[p] = w2f[fb + p * 32];
    };
    ldB(bfa, 0);

    asm volatile("cp.async.wait_group 0;" ::: "memory");
    __syncthreads();

    for (int p = 0; p < 4; p++) {
        float acc[2][16][4];
        #pragma unroll
        for (int mt = 0; mt < 2; mt++)
            #pragma unroll
            for (int nt = 0; nt < 16; nt++)
                #pragma unroll
                for (int q = 0; q < 4; q++) acc[mt][nt][q] = 0.0f;

        const __half* ar = s_arow + p * 512;

        #pragma unroll 8
        for (int kb = 0; kb < 32; kb++) {
            uint4* cur = (kb & 1) ? bfb : bfa;
            uint4* nxt = (kb & 1) ? bfa : bfb;
            ldB(nxt, (kb < 31) ? kb + 1 : 0);      // chains into the next pass

            // ---- A fragments (k-permuted): one LDS.64 per source ----
            const int st = kb >> 2;
            const int ko = (kb & 3) * 16 + tg * 4;
            const __half* bps = s_bp + st * 5120 + ko;
            const uint2 ua = *(const uint2*)&ar[kb * 16 + tg * 4];
            const uint2 u0 = *(const uint2*)&bps[(r0     ) * 80];
            const uint2 u1 = *(const uint2*)&bps[(r0 +  8) * 80];
            const uint2 u2 = *(const uint2*)&bps[(r0 + 16) * 80];
            const uint2 u3 = *(const uint2*)&bps[(r0 + 24) * 80];
            uint32_t a0[4], a1[4];
            a0[0] = fragAB(ua.x, u0.x);
            a0[1] = fragAB(ua.x, u1.x);
            a0[2] = fragAB(ua.y, u0.y);
            a0[3] = fragAB(ua.y, u1.y);
            a1[0] = fragAB(ua.x, u2.x);
            a1[1] = fragAB(ua.x, u3.x);
            a1[2] = fragAB(ua.y, u2.y);
            a1[3] = fragAB(ua.y, u3.y);

            // ---- 32 MMAs on the current B slice ----
            #pragma unroll
            for (int q = 0; q < 8; q++) {
                mma_f16(acc[0][2 * q + 0], a0, cur[q].x, cur[q].y);
                mma_f16(acc[0][2 * q + 1], a0, cur[q].z, cur[q].w);
                mma_f16(acc[1][2 * q + 0], a1, cur[q].x, cur[q].y);
                mma_f16(acc[1][2 * q + 1], a1, cur[q].z, cur[q].w);
            }
        }

        // ---- epilogue pass p: out[n0g+p, m0+row] ----
        float p0 = 0.0f, p1 = 0.0f, p2s = 0.0f, p3s = 0.0f;
        #pragma unroll
        for (int nt = 0; nt < 16; nt++) {
            const int j = wc * 128 + nt * 8 + 2 * tg;
            const float b2a = s_b2[j], b2b = s_b2[j + 1];
            const float w3a = s_w3[j], w3b = s_w3[j + 1];
            const float* c0 = acc[0][nt];
            const float* c1 = acc[1][nt];
            p0  += fmaxf(c0[0] + b2a, 0.0f) * w3a + fmaxf(c0[1] + b2b, 0.0f) * w3b;
            p1  += fmaxf(c0[2] + b2a, 0.0f) * w3a + fmaxf(c0[3] + b2b, 0.0f) * w3b;
            p2s += fmaxf(c1[0] + b2a, 0.0f) * w3a + fmaxf(c1[1] + b2b, 0.0f) * w3b;
            p3s += fmaxf(c1[2] + b2a, 0.0f) * w3a + fmaxf(c1[3] + b2b, 0.0f) * w3b;
        }
        #pragma unroll
        for (int off = 1; off < 4; off <<= 1) {
            p0  += __shfl_xor_sync(0xffffffffu, p0, off);
            p1  += __shfl_xor_sync(0xffffffffu, p1, off);
            p2s += __shfl_xor_sync(0xffffffffu, p2s, off);
            p3s += __shfl_xor_sync(0xffffffffu, p3s, off);
        }

        // double-buffered s_part by pass parity -> single barrier per pass.
        // Buffer p&1 was last READ in pass p-2, ordered by pass p-1's barrier.
        float* sp = s_part + (p & 1) * 128;
        if (tg == 0) {
            sp[(r0     ) * 2 + wc] = p0;
            sp[(r0 +  8) * 2 + wc] = p1;
            sp[(r0 + 16) * 2 + wc] = p2s;
            sp[(r0 + 24) * 2 + wc] = p3s;
        }
        __syncthreads();
        if (tid < 64) {
            float v = sp[tid * 2 + 0] + sp[tid * 2 + 1] + b3[0];
            out[(size_t)(n0g + p) * M_DIM + m0 + tid] = v;
        }
    }
}

// ============================================================================
// Launch
// ============================================================================
extern "C" void kernel_launch(void* const* d_in, const int* in_sizes, int n_in,
                              void* d_out, int out_size) {
    const float* PhiA = (const float*)d_in[0];
    const float* PhiB = (const float*)d_in[1];
    const float* W1a  = (const float*)d_in[2];
    const float* W1b  = (const float*)d_in[3];
    const float* b1   = (const float*)d_in[4];
    const float* W2   = (const float*)d_in[5];
    const float* b2   = (const float*)d_in[6];
    const float* W3   = (const float*)d_in[7];
    const float* b3   = (const float*)d_in[8];
    float* out = (float*)d_out;

    __half* aprojh = nullptr;
    __half* bprojh = nullptr;
    uint4 *w2f = nullptr, *w1af = nullptr, *w1bf = nullptr;
    cudaGetSymbolAddress((void**)&aprojh, g_aprojh);
    cudaGetSymbolAddress((void**)&bprojh, g_bprojh);
    cudaGetSymbolAddress((void**)&w2f, g_w2frag);
    cudaGetSymbolAddress((void**)&w1af, g_w1afrag);
    cudaGetSymbolAddress((void**)&w1bf, g_w1bfrag);

    // fragment all weight matrices (W2, W1a, W1b)
    wfrag_kernel<<<dim3(36, 8, 3), 128>>>(W2, W1a, W1b, w2f, w1af, w1bf);
    // tensor-core projections -> k-permuted fp16 aproj/bproj
    proj_mma_kernel<<<dim3((B_DIM * N_DIM + B_DIM * M_DIM) / 32, H1_DIM / 128), 128>>>(
        PhiA, PhiB, b1, w1af, w1bf, aprojh, bprojh);
    // fused pairwise MLP (4n x 64m tiles, resident bp slab)
    cudaFuncSetAttribute(pair_mlp_main, cudaFuncAttributeMaxDynamicSharedMemorySize,
                         SMEM_MAIN);
    pair_mlp_main<<<B_DIM * N_DIM * M_DIM / (4 * 64), 128, SMEM_MAIN>>>(
        aprojh, bprojh, w2f, b2, W3, b3, out);
}